// round 6
// baseline (speedup 1.0000x reference)
#include <cuda_runtime.h>
#include <cuda_bf16.h>
#include <math.h>
#include <stdint.h>

#define S_LEN 2048
#define D_DIM 2048
#define H_NUM 16
#define HD    128
#define B_NUM 2
#define M_ROWS (B_NUM * S_LEN)   // 4096
#define KDIM  2048
#define BH_NUM (B_NUM * H_NUM)   // 32

// ---------------------------------------------------------------------------
// Scratch (device globals: no allocation allowed)
// ---------------------------------------------------------------------------
__device__ __nv_bfloat16 g_ah[(size_t)M_ROWS * KDIM];          // A hi (x, then attn-out)
__device__ __nv_bfloat16 g_al[(size_t)M_ROWS * KDIM];          // A lo
__device__ __nv_bfloat16 g_wth[(size_t)4 * D_DIM * KDIM];      // W^T hi
__device__ __nv_bfloat16 g_wtl[(size_t)4 * D_DIM * KDIM];      // W^T lo
__device__ __nv_bfloat16 g_qh[(size_t)BH_NUM * S_LEN * HD];
__device__ __nv_bfloat16 g_ql[(size_t)BH_NUM * S_LEN * HD];
__device__ __nv_bfloat16 g_kh[(size_t)BH_NUM * S_LEN * HD];
__device__ __nv_bfloat16 g_kl[(size_t)BH_NUM * S_LEN * HD];
__device__ __nv_bfloat16 g_vh[(size_t)BH_NUM * S_LEN * HD];
__device__ __nv_bfloat16 g_vl[(size_t)BH_NUM * S_LEN * HD];

// ---------------------------------------------------------------------------
// Helpers (plain sm_103-legal: cp.async, ldmatrix, mma.sync bf16)
// ---------------------------------------------------------------------------
__device__ __forceinline__ uint32_t smem_u32(const void* p) {
    uint32_t a;
    asm("{ .reg .u64 t; cvta.to.shared.u64 t, %1; cvt.u32.u64 %0, t; }"
        : "=r"(a) : "l"(p));
    return a;
}

__device__ __forceinline__ void cp16(uint32_t sm_dst, const void* g_src) {
    asm volatile("cp.async.cg.shared.global [%0], [%1], 16;"
                 :: "r"(sm_dst), "l"(g_src));
}
#define CP_COMMIT() asm volatile("cp.async.commit_group;" ::: "memory")
#define CP_WAIT1()  asm volatile("cp.async.wait_group 1;" ::: "memory")
#define CP_WAIT0()  asm volatile("cp.async.wait_group 0;" ::: "memory")

__device__ __forceinline__ void ldsm4(uint32_t* r, uint32_t addr) {
    asm volatile("ldmatrix.sync.aligned.m8n8.x4.shared.b16 {%0,%1,%2,%3}, [%4];"
                 : "=r"(r[0]), "=r"(r[1]), "=r"(r[2]), "=r"(r[3]) : "r"(addr));
}
__device__ __forceinline__ void ldsm4t(uint32_t* r, uint32_t addr) {
    asm volatile("ldmatrix.sync.aligned.m8n8.x4.trans.shared.b16 {%0,%1,%2,%3}, [%4];"
                 : "=r"(r[0]), "=r"(r[1]), "=r"(r[2]), "=r"(r[3]) : "r"(addr));
}

__device__ __forceinline__ void mma_bf16(float* d, const uint32_t* a,
                                         const uint32_t* b) {
    asm volatile(
        "mma.sync.aligned.m16n8k16.row.col.f32.bf16.bf16.f32 "
        "{%0,%1,%2,%3}, {%4,%5,%6,%7}, {%8,%9}, {%0,%1,%2,%3};"
        : "+f"(d[0]), "+f"(d[1]), "+f"(d[2]), "+f"(d[3])
        : "r"(a[0]), "r"(a[1]), "r"(a[2]), "r"(a[3]), "r"(b[0]), "r"(b[1]));
}

// ---------------------------------------------------------------------------
// bf16-split GEMM via mma.sync. Mainloop identical to the Round-4/5 version
// (PASSED twice). Epilogue: qkv_mode=1 applies RoPE (z=0 Q scaled, z=1 K) or
// plain convert (z=2 V) and writes bf16 hi/lo pairs to [BH,S,HD] buffers.
// ---------------------------------------------------------------------------
#define MG_BK 32
#define MG_NC (KDIM / MG_BK)        // 64
#define MAT_BYTES (128 * 80)
#define STAGE_B (4 * MAT_BYTES)
#define MG_SMEM (3 * STAGE_B)       // 122880

__device__ __forceinline__ void mg_load(
    uint32_t st, const __nv_bfloat16* Ah, const __nv_bfloat16* Al,
    const __nv_bfloat16* Bh, const __nv_bfloat16* Bl,
    int m0, int n0, int k0, int tid)
{
    int lrow = tid >> 2;
    int lch  = tid & 3;
#pragma unroll
    for (int i = 0; i < 2; i++) {
        int r = lrow + 64 * i;
        uint32_t off = (uint32_t)r * 80 + lch * 16;
        size_t ga = (size_t)(m0 + r) * KDIM + k0 + lch * 8;
        size_t gb = (size_t)(n0 + r) * KDIM + k0 + lch * 8;
        cp16(st + off,                 Ah + ga);
        cp16(st + MAT_BYTES + off,     Al + ga);
        cp16(st + 2 * MAT_BYTES + off, Bh + gb);
        cp16(st + 3 * MAT_BYTES + off, Bl + gb);
    }
}

__global__ __launch_bounds__(256)
void mma_gemm_kernel(const __nv_bfloat16* __restrict__ Ah,
                     const __nv_bfloat16* __restrict__ Al,
                     const __nv_bfloat16* __restrict__ WtH,
                     const __nv_bfloat16* __restrict__ WtL,
                     __nv_bfloat16* H0, __nv_bfloat16* L0,
                     __nv_bfloat16* H1, __nv_bfloat16* L1,
                     __nv_bfloat16* H2, __nv_bfloat16* L2,
                     float* Cf,
                     int wbase, int qkv_mode)
{
    extern __shared__ __align__(256) char smem[];
    uint32_t sb = smem_u32(smem);
    int tid = threadIdx.x;
    int wid = tid >> 5, lane = tid & 31;
    int z = blockIdx.z;

    const __nv_bfloat16* Bh = WtH + (size_t)(wbase + z) * D_DIM * KDIM;
    const __nv_bfloat16* Bl = WtL + (size_t)(wbase + z) * D_DIM * KDIM;
    int m0 = blockIdx.y * 128;
    int n0 = blockIdx.x * 128;

    int wm = wid & 3;
    int wn = wid >> 2;

    float acc[2][8][4];
#pragma unroll
    for (int i = 0; i < 2; i++)
#pragma unroll
        for (int j = 0; j < 8; j++)
#pragma unroll
            for (int t = 0; t < 4; t++) acc[i][j][t] = 0.f;

    mg_load(sb,           Ah, Al, Bh, Bl, m0, n0, 0,     tid); CP_COMMIT();
    mg_load(sb + STAGE_B, Ah, Al, Bh, Bl, m0, n0, MG_BK, tid); CP_COMMIT();

    int a_row  = wm * 32 + (lane & 15);
    uint32_t a_koff = ((lane >> 4) & 1) * 16;
    int b_row  = wn * 64 + (lane & 7) + (((lane >> 4) & 1) << 3);
    uint32_t b_koff = ((lane >> 3) & 1) * 16;

    for (int c = 0; c < MG_NC; c++) {
        if (c + 2 >= MG_NC) { CP_WAIT0(); } else { CP_WAIT1(); }
        __syncthreads();
        uint32_t u = sb + (uint32_t)(c % 3) * STAGE_B;
        uint32_t uAh = u, uAl = u + MAT_BYTES;
        uint32_t uBh = u + 2 * MAT_BYTES, uBl = u + 3 * MAT_BYTES;

#pragma unroll
        for (int ks = 0; ks < 2; ks++) {
            uint32_t kb = ks * 32;
            uint32_t ah[2][4], al[2][4], bh[4][4], bl[4][4];
            uint32_t ao = (uint32_t)a_row * 80 + a_koff + kb;
            ldsm4(ah[0], uAh + ao);
            ldsm4(ah[1], uAh + ao + 16 * 80);
            ldsm4(al[0], uAl + ao);
            ldsm4(al[1], uAl + ao + 16 * 80);
#pragma unroll
            for (int j = 0; j < 4; j++) {
                uint32_t bo = (uint32_t)(b_row + j * 16) * 80 + b_koff + kb;
                ldsm4(bh[j], uBh + bo);
                ldsm4(bl[j], uBl + bo);
            }
#pragma unroll
            for (int i = 0; i < 2; i++)
#pragma unroll
                for (int j = 0; j < 4; j++) {
                    mma_bf16(acc[i][2 * j],     ah[i], &bh[j][0]);
                    mma_bf16(acc[i][2 * j + 1], ah[i], &bh[j][2]);
                    mma_bf16(acc[i][2 * j],     ah[i], &bl[j][0]);
                    mma_bf16(acc[i][2 * j + 1], ah[i], &bl[j][2]);
                    mma_bf16(acc[i][2 * j],     al[i], &bh[j][0]);
                    mma_bf16(acc[i][2 * j + 1], al[i], &bh[j][2]);
                }
        }

        if (c + 2 < MG_NC) {
            mg_load(sb + (uint32_t)((c + 2) % 3) * STAGE_B,
                    Ah, Al, Bh, Bl, m0, n0, (c + 2) * MG_BK, tid);
            CP_COMMIT();
        }
    }

    int r0 = m0 + wm * 32 + (lane >> 2);
    int c0 = n0 + wn * 64 + (lane & 3) * 2;

    if (!qkv_mode) {
#pragma unroll
        for (int i = 0; i < 2; i++) {
#pragma unroll
            for (int j = 0; j < 8; j++) {
                int gn = c0 + j * 8;
#pragma unroll
                for (int half = 0; half < 2; half++) {
                    int gm = r0 + i * 16 + half * 8;
                    *(float2*)&Cf[(size_t)gm * D_DIM + gn] =
                        make_float2(acc[i][j][2 * half], acc[i][j][2 * half + 1]);
                }
            }
        }
    } else {
        __nv_bfloat16* HZ = (z == 0) ? H0 : ((z == 1) ? H1 : H2);
        __nv_bfloat16* LZ = (z == 0) ? L0 : ((z == 1) ? L1 : L2);
        const float nlog = -9.210340372f;           // -ln(10000)
        const float qscale = 0.08838834764831845f;  // 1/sqrt(128)
#pragma unroll
        for (int j = 0; j < 8; j++) {
            int gn = c0 + j * 8;
            int hd = gn & 127;
            int h  = gn >> 7;
            float f0 = 0.f, f1 = 0.f;
            if (z < 2) {
                int t0 = hd & 63;      // hd even -> t0 even <= 62
                f0 = __expf(nlog * (float)t0 * (1.0f / 64.0f));
                f1 = __expf(nlog * (float)(t0 + 1) * (1.0f / 64.0f));
            }
#pragma unroll
            for (int i = 0; i < 2; i++) {
#pragma unroll
                for (int half = 0; half < 2; half++) {
                    int gm = r0 + i * 16 + half * 8;
                    int b = gm >> 11, s = gm & 2047;
                    float x0 = acc[i][j][2 * half];
                    float x1 = acc[i][j][2 * half + 1];
                    float y0 = x0, y1 = x1;
                    if (z < 2) {
                        float a0 = (float)s * f0;
                        float a1 = (float)s * f1;
                        float c0f, s0f, c1f, s1f;
                        sincosf(a0, &s0f, &c0f);
                        sincosf(a1, &s1f, &c1f);
                        y0 = x0 * c0f - x1 * s0f;   // even: x*cos - x_odd*sin
                        y1 = x1 * c1f + x0 * s1f;   // odd:  x*cos + x_even*sin
                        if (z == 0) { y0 *= qscale; y1 *= qscale; }
                    }
                    __nv_bfloat16 hh0 = __float2bfloat16(y0);
                    __nv_bfloat16 hh1 = __float2bfloat16(y1);
                    __nv_bfloat16 ll0 = __float2bfloat16(y0 - __bfloat162float(hh0));
                    __nv_bfloat16 ll1 = __float2bfloat16(y1 - __bfloat162float(hh1));
                    size_t off = (((size_t)(b * H_NUM + h)) * S_LEN + s) * HD + hd;
                    *(__nv_bfloat162*)(HZ + off) = __nv_bfloat162(hh0, hh1);
                    *(__nv_bfloat162*)(LZ + off) = __nv_bfloat162(ll0, ll1);
                }
            }
        }
    }
}

// ---------------------------------------------------------------------------
// fp32 -> (hi, lo) bf16 split, 4 elems/thread (x input only)
// ---------------------------------------------------------------------------
__global__ void split_kernel(const float* __restrict__ X,
                             __nv_bfloat16* __restrict__ Hh,
                             __nv_bfloat16* __restrict__ Ll)
{
    size_t i = ((size_t)blockIdx.x * blockDim.x + threadIdx.x) * 4;
    float4 v = *(const float4*)(X + i);
    __nv_bfloat16 h0 = __float2bfloat16(v.x);
    __nv_bfloat16 h1 = __float2bfloat16(v.y);
    __nv_bfloat16 h2 = __float2bfloat16(v.z);
    __nv_bfloat16 h3 = __float2bfloat16(v.w);
    __nv_bfloat16 l0 = __float2bfloat16(v.x - __bfloat162float(h0));
    __nv_bfloat16 l1 = __float2bfloat16(v.y - __bfloat162float(h1));
    __nv_bfloat16 l2 = __float2bfloat16(v.z - __bfloat162float(h2));
    __nv_bfloat16 l3 = __float2bfloat16(v.w - __bfloat162float(h3));
    __nv_bfloat162* hp = (__nv_bfloat162*)(Hh + i);
    __nv_bfloat162* lp = (__nv_bfloat162*)(Ll + i);
    hp[0] = __nv_bfloat162(h0, h1); hp[1] = __nv_bfloat162(h2, h3);
    lp[0] = __nv_bfloat162(l0, l1); lp[1] = __nv_bfloat162(l2, l3);
}

// ---------------------------------------------------------------------------
// Weight transpose + split (unchanged)
// ---------------------------------------------------------------------------
__global__ void wtrans_kernel(const float* __restrict__ W0, const float* __restrict__ W1,
                              const float* __restrict__ W2, const float* __restrict__ W3,
                              __nv_bfloat16* __restrict__ TH,
                              __nv_bfloat16* __restrict__ TL)
{
    __shared__ float t[32][33];
    int z = blockIdx.z;
    const float* W = (z == 0) ? W0 : (z == 1 ? W1 : (z == 2 ? W2 : W3));
    __nv_bfloat16* th = TH + (size_t)z * D_DIM * KDIM;
    __nv_bfloat16* tl = TL + (size_t)z * D_DIM * KDIM;
    int k0 = blockIdx.y * 32, n0 = blockIdx.x * 32;
    int tx = threadIdx.x, ty = threadIdx.y;
#pragma unroll
    for (int i = 0; i < 4; i++)
        t[ty + 8 * i][tx] = W[(size_t)(k0 + ty + 8 * i) * D_DIM + n0 + tx];
    __syncthreads();
#pragma unroll
    for (int i = 0; i < 4; i++) {
        float v = t[tx][ty + 8 * i];
        __nv_bfloat16 h = __float2bfloat16(v);
        __nv_bfloat16 l = __float2bfloat16(v - __bfloat162float(h));
        size_t o = (size_t)(n0 + ty + 8 * i) * KDIM + k0 + tx;
        th[o] = h;
        tl[o] = l;
    }
}

// ---------------------------------------------------------------------------
// Tensor-core flash attention (bf16 split, fp32 softmax), causal.
// Epilogue writes attn output directly as bf16 hi/lo into [B,S,D] buffers.
// ---------------------------------------------------------------------------
#define FR_STRIDE 272                       // 128 bf16 cols + 16B pad
#define FQ_BYTES  (128 * FR_STRIDE)         // 34816
#define FKV_MAT   (64 * FR_STRIDE)          // 17408
#define FSTAGE    (4 * FKV_MAT)             // Kh,Kl,Vh,Vl = 69632
#define FA2_SMEM  (2 * FQ_BYTES + 2 * FSTAGE)  // 208896

__device__ __forceinline__ void fa_load_kv(
    uint32_t st, const __nv_bfloat16* KH, const __nv_bfloat16* KL,
    const __nv_bfloat16* VH, const __nv_bfloat16* VL,
    int bh, int kb, int tid)
{
#pragma unroll
    for (int i = 0; i < 4; i++) {
        int idx = tid + i * 256;          // 0..1023
        int r = idx >> 4, ch = idx & 15;
        uint32_t off = (uint32_t)r * FR_STRIDE + ch * 16;
        size_t g = ((size_t)bh * S_LEN + kb * 64 + r) * HD + ch * 8;
        cp16(st + off,               KH + g);
        cp16(st + FKV_MAT + off,     KL + g);
        cp16(st + 2 * FKV_MAT + off, VH + g);
        cp16(st + 3 * FKV_MAT + off, VL + g);
    }
}

__global__ __launch_bounds__(256, 1)
void flash_mma_kernel(const __nv_bfloat16* __restrict__ QH,
                      const __nv_bfloat16* __restrict__ QL,
                      const __nv_bfloat16* __restrict__ KH,
                      const __nv_bfloat16* __restrict__ KL,
                      const __nv_bfloat16* __restrict__ VH,
                      const __nv_bfloat16* __restrict__ VL,
                      __nv_bfloat16* __restrict__ AH,
                      __nv_bfloat16* __restrict__ AL)
{
    extern __shared__ __align__(256) char smem[];
    uint32_t sb = smem_u32(smem);
    const uint32_t uQH = sb, uQL = sb + FQ_BYTES;
    const uint32_t uST0 = sb + 2 * FQ_BYTES;

    int tid = threadIdx.x;
    int wid = tid >> 5, lane = tid & 31;
    int qb = 15 - blockIdx.x;        // big blocks first
    int bh = blockIdx.y;
    int nkb = 2 * qb + 2;

#pragma unroll
    for (int i = 0; i < 8; i++) {
        int idx = tid + i * 256;      // 0..2047
        int r = idx >> 4, ch = idx & 15;
        uint32_t off = (uint32_t)r * FR_STRIDE + ch * 16;
        size_t g = ((size_t)bh * S_LEN + qb * 128 + r) * HD + ch * 8;
        cp16(uQH + off, QH + g);
        cp16(uQL + off, QL + g);
    }
    CP_COMMIT();
    fa_load_kv(uST0, KH, KL, VH, VL, bh, 0, tid); CP_COMMIT();
    if (nkb > 1) { fa_load_kv(uST0 + FSTAGE, KH, KL, VH, VL, bh, 1, tid); CP_COMMIT(); }

    float accO[16][4];
#pragma unroll
    for (int j = 0; j < 16; j++)
#pragma unroll
        for (int t = 0; t < 4; t++) accO[j][t] = 0.f;
    float m0v = -INFINITY, m1v = -INFINITY, l0v = 0.f, l1v = 0.f;

    uint32_t q_ao = (uint32_t)(wid * 16 + (lane & 15)) * FR_STRIDE + ((lane >> 4) & 1) * 16;
    uint32_t k_bo = (uint32_t)((lane & 7) + (((lane >> 4) & 1) << 3)) * FR_STRIDE
                    + ((lane >> 3) & 1) * 16;
    uint32_t v_to = (uint32_t)(lane & 15) * FR_STRIDE + ((lane >> 4) & 1) * 16;

    if (nkb > 1) { CP_WAIT1(); } else { CP_WAIT0(); }
    __syncthreads();

    for (int kb = 0; kb < nkb; kb++) {
        uint32_t st = uST0 + (uint32_t)(kb & 1) * FSTAGE;
        uint32_t stKH = st, stKL = st + FKV_MAT;
        uint32_t stVH = st + 2 * FKV_MAT, stVL = st + 3 * FKV_MAT;

        float accS[8][4];
#pragma unroll
        for (int j = 0; j < 8; j++)
#pragma unroll
            for (int t = 0; t < 4; t++) accS[j][t] = 0.f;

#pragma unroll
        for (int ks = 0; ks < 8; ks++) {
            uint32_t qh[4], ql[4];
            ldsm4(qh, uQH + q_ao + ks * 32);
            ldsm4(ql, uQL + q_ao + ks * 32);
#pragma unroll
            for (int j = 0; j < 4; j++) {
                uint32_t kh[4], kl[4];
                uint32_t bo = k_bo + (uint32_t)j * 16 * FR_STRIDE + ks * 32;
                ldsm4(kh, stKH + bo);
                ldsm4(kl, stKL + bo);
                mma_bf16(accS[2 * j],     qh, &kh[0]);
                mma_bf16(accS[2 * j + 1], qh, &kh[2]);
                mma_bf16(accS[2 * j],     qh, &kl[0]);
                mma_bf16(accS[2 * j + 1], qh, &kl[2]);
                mma_bf16(accS[2 * j],     ql, &kh[0]);
                mma_bf16(accS[2 * j + 1], ql, &kh[2]);
            }
        }

        if (kb >= 2 * qb) {
            int grow = qb * 128 + wid * 16 + (lane >> 2);
#pragma unroll
            for (int j = 0; j < 8; j++) {
                int col = kb * 64 + j * 8 + ((lane & 3) << 1);
                if (col     > grow)     accS[j][0] = -INFINITY;
                if (col + 1 > grow)     accS[j][1] = -INFINITY;
                if (col     > grow + 8) accS[j][2] = -INFINITY;
                if (col + 1 > grow + 8) accS[j][3] = -INFINITY;
            }
        }

        float rm0 = -INFINITY, rm1 = -INFINITY;
#pragma unroll
        for (int j = 0; j < 8; j++) {
            rm0 = fmaxf(rm0, fmaxf(accS[j][0], accS[j][1]));
            rm1 = fmaxf(rm1, fmaxf(accS[j][2], accS[j][3]));
        }
        rm0 = fmaxf(rm0, __shfl_xor_sync(0xffffffffu, rm0, 1));
        rm0 = fmaxf(rm0, __shfl_xor_sync(0xffffffffu, rm0, 2));
        rm1 = fmaxf(rm1, __shfl_xor_sync(0xffffffffu, rm1, 1));
        rm1 = fmaxf(rm1, __shfl_xor_sync(0xffffffffu, rm1, 2));

        float mn0 = fmaxf(m0v, rm0), mn1 = fmaxf(m1v, rm1);
        float al0 = __expf(m0v - mn0), al1 = __expf(m1v - mn1);
        m0v = mn0; m1v = mn1;

        float rs0 = 0.f, rs1 = 0.f;
#pragma unroll
        for (int j = 0; j < 8; j++) {
            accS[j][0] = __expf(accS[j][0] - mn0);
            accS[j][1] = __expf(accS[j][1] - mn0);
            accS[j][2] = __expf(accS[j][2] - mn1);
            accS[j][3] = __expf(accS[j][3] - mn1);
            rs0 += accS[j][0] + accS[j][1];
            rs1 += accS[j][2] + accS[j][3];
        }
        rs0 += __shfl_xor_sync(0xffffffffu, rs0, 1);
        rs0 += __shfl_xor_sync(0xffffffffu, rs0, 2);
        rs1 += __shfl_xor_sync(0xffffffffu, rs1, 1);
        rs1 += __shfl_xor_sync(0xffffffffu, rs1, 2);
        l0v = l0v * al0 + rs0;
        l1v = l1v * al1 + rs1;

#pragma unroll
        for (int j = 0; j < 16; j++) {
            accO[j][0] *= al0; accO[j][1] *= al0;
            accO[j][2] *= al1; accO[j][3] *= al1;
        }

        uint32_t pa_h[8][2], pa_l[8][2];
#pragma unroll
        for (int j = 0; j < 8; j++) {
            __nv_bfloat16 h0 = __float2bfloat16(accS[j][0]);
            __nv_bfloat16 h1 = __float2bfloat16(accS[j][1]);
            __nv_bfloat16 h2 = __float2bfloat16(accS[j][2]);
            __nv_bfloat16 h3 = __float2bfloat16(accS[j][3]);
            __nv_bfloat16 e0 = __float2bfloat16(accS[j][0] - __bfloat162float(h0));
            __nv_bfloat16 e1 = __float2bfloat16(accS[j][1] - __bfloat162float(h1));
            __nv_bfloat16 e2 = __float2bfloat16(accS[j][2] - __bfloat162float(h2));
            __nv_bfloat16 e3 = __float2bfloat16(accS[j][3] - __bfloat162float(h3));
            pa_h[j][0] = ((uint32_t)__bfloat16_as_ushort(h1) << 16) | __bfloat16_as_ushort(h0);
            pa_h[j][1] = ((uint32_t)__bfloat16_as_ushort(h3) << 16) | __bfloat16_as_ushort(h2);
            pa_l[j][0] = ((uint32_t)__bfloat16_as_ushort(e1) << 16) | __bfloat16_as_ushort(e0);
            pa_l[j][1] = ((uint32_t)__bfloat16_as_ushort(e3) << 16) | __bfloat16_as_ushort(e2);
        }

#pragma unroll
        for (int ks = 0; ks < 4; ks++) {
            uint32_t ah4[4] = { pa_h[2 * ks][0], pa_h[2 * ks][1],
                                pa_h[2 * ks + 1][0], pa_h[2 * ks + 1][1] };
            uint32_t al4[4] = { pa_l[2 * ks][0], pa_l[2 * ks][1],
                                pa_l[2 * ks + 1][0], pa_l[2 * ks + 1][1] };
#pragma unroll
            for (int j2 = 0; j2 < 8; j2++) {
                uint32_t vh[4], vl[4];
                uint32_t vo = v_to + (uint32_t)ks * 16 * FR_STRIDE + j2 * 32;
                ldsm4t(vh, stVH + vo);
                ldsm4t(vl, stVL + vo);
                mma_bf16(accO[2 * j2],     ah4, &vh[0]);
                mma_bf16(accO[2 * j2 + 1], ah4, &vh[2]);
                mma_bf16(accO[2 * j2],     ah4, &vl[0]);
                mma_bf16(accO[2 * j2 + 1], ah4, &vl[2]);
                mma_bf16(accO[2 * j2],     al4, &vh[0]);
                mma_bf16(accO[2 * j2 + 1], al4, &vh[2]);
            }
        }

        __syncthreads();
        if (kb + 2 < nkb) {
            fa_load_kv(st, KH, KL, VH, VL, bh, kb + 2, tid);
            CP_COMMIT();
        }
        if (kb + 1 < nkb) {
            if (kb + 2 < nkb) { CP_WAIT1(); } else { CP_WAIT0(); }
            __syncthreads();
        }
    }

    // ---- epilogue: normalize, bf16 hi/lo split, write [B][S][D] ----
    int b = bh >> 4, h = bh & 15;
    int srow = qb * 128 + wid * 16 + (lane >> 2);
    float inv0 = 1.0f / l0v, inv1 = 1.0f / l1v;
#pragma unroll
    for (int j = 0; j < 16; j++) {
        int col = h * HD + j * 8 + ((lane & 3) << 1);
        size_t o0 = ((size_t)b * S_LEN + srow) * D_DIM + col;
        size_t o1 = ((size_t)b * S_LEN + srow + 8) * D_DIM + col;
        float v00 = accO[j][0] * inv0, v01 = accO[j][1] * inv0;
        float v10 = accO[j][2] * inv1, v11 = accO[j][3] * inv1;
        __nv_bfloat16 h00 = __float2bfloat16(v00);
        __nv_bfloat16 h01 = __float2bfloat16(v01);
        __nv_bfloat16 h10 = __float2bfloat16(v10);
        __nv_bfloat16 h11 = __float2bfloat16(v11);
        __nv_bfloat16 l00 = __float2bfloat16(v00 - __bfloat162float(h00));
        __nv_bfloat16 l01 = __float2bfloat16(v01 - __bfloat162float(h01));
        __nv_bfloat16 l10 = __float2bfloat16(v10 - __bfloat162float(h10));
        __nv_bfloat16 l11 = __float2bfloat16(v11 - __bfloat162float(h11));
        *(__nv_bfloat162*)(AH + o0) = __nv_bfloat162(h00, h01);
        *(__nv_bfloat162*)(AL + o0) = __nv_bfloat162(l00, l01);
        *(__nv_bfloat162*)(AH + o1) = __nv_bfloat162(h10, h11);
        *(__nv_bfloat162*)(AL + o1) = __nv_bfloat162(l10, l11);
    }
}

// ---------------------------------------------------------------------------
extern "C" void kernel_launch(void* const* d_in, const int* in_sizes, int n_in,
                              void* d_out, int out_size)
{
    const float* x  = (const float*)d_in[0];
    const float* Wq = (const float*)d_in[1];
    const float* Wk = (const float*)d_in[2];
    const float* Wv = (const float*)d_in[3];
    const float* Wo = (const float*)d_in[4];
    float* out = (float*)d_out;

    __nv_bfloat16 *pah, *pal, *pwh, *pwl;
    __nv_bfloat16 *pqh, *pql, *pkh, *pkl, *pvh, *pvl;
    cudaGetSymbolAddress((void**)&pah, g_ah);
    cudaGetSymbolAddress((void**)&pal, g_al);
    cudaGetSymbolAddress((void**)&pwh, g_wth);
    cudaGetSymbolAddress((void**)&pwl, g_wtl);
    cudaGetSymbolAddress((void**)&pqh, g_qh);
    cudaGetSymbolAddress((void**)&pql, g_ql);
    cudaGetSymbolAddress((void**)&pkh, g_kh);
    cudaGetSymbolAddress((void**)&pkl, g_kl);
    cudaGetSymbolAddress((void**)&pvh, g_vh);
    cudaGetSymbolAddress((void**)&pvl, g_vl);

    cudaFuncSetAttribute(mma_gemm_kernel,
                         cudaFuncAttributeMaxDynamicSharedMemorySize, MG_SMEM);
    cudaFuncSetAttribute(flash_mma_kernel,
                         cudaFuncAttributeMaxDynamicSharedMemorySize, FA2_SMEM);

    // 0) bf16 split of x
    split_kernel<<<(M_ROWS * KDIM / 4) / 256, 256>>>(x, pah, pal);

    // 1) weight transpose + split
    wtrans_kernel<<<dim3(D_DIM / 32, KDIM / 32, 4), dim3(32, 8)>>>(
        Wq, Wk, Wv, Wo, pwh, pwl);

    // 2) QKV projections + fused RoPE/scale/bf16-split epilogue
    mma_gemm_kernel<<<dim3(D_DIM / 128, M_ROWS / 128, 3), 256, MG_SMEM>>>(
        pah, pal, pwh, pwl,
        pqh, pql, pkh, pkl, pvh, pvl, (float*)nullptr, 0, 1);

    // 3) tensor-core causal flash attention (writes bf16 hi/lo attn-out)
    flash_mma_kernel<<<dim3(S_LEN / 128, BH_NUM), 256, FA2_SMEM>>>(
        pqh, pql, pkh, pkl, pvh, pvl, pah, pal);

    // 4) O projection -> d_out (fp32)
    mma_gemm_kernel<<<dim3(D_DIM / 128, M_ROWS / 128, 1), 256, MG_SMEM>>>(
        pah, pal, pwh, pwl,
        (__nv_bfloat16*)nullptr, (__nv_bfloat16*)nullptr,
        (__nv_bfloat16*)nullptr, (__nv_bfloat16*)nullptr,
        (__nv_bfloat16*)nullptr, (__nv_bfloat16*)nullptr,
        out, 3, 0);
}

// round 8
// speedup vs baseline: 1.0841x; 1.0841x over previous
#include <cuda_runtime.h>
#include <cuda_bf16.h>
#include <math.h>
#include <stdint.h>

#define S_LEN 2048
#define D_DIM 2048
#define H_NUM 16
#define HD    128
#define B_NUM 2
#define M_ROWS (B_NUM * S_LEN)   // 4096
#define KDIM  2048
#define BH_NUM (B_NUM * H_NUM)   // 32

// ---------------------------------------------------------------------------
// Scratch (device globals: no allocation allowed)
// ---------------------------------------------------------------------------
__device__ __nv_bfloat16 g_ah[(size_t)M_ROWS * KDIM];          // A hi (x, then attn-out)
__device__ __nv_bfloat16 g_al[(size_t)M_ROWS * KDIM];          // A lo
__device__ __nv_bfloat16 g_wth[(size_t)4 * D_DIM * KDIM];      // W^T hi
__device__ __nv_bfloat16 g_wtl[(size_t)4 * D_DIM * KDIM];      // W^T lo
__device__ __nv_bfloat16 g_qh[(size_t)BH_NUM * S_LEN * HD];
__device__ __nv_bfloat16 g_ql[(size_t)BH_NUM * S_LEN * HD];
__device__ __nv_bfloat16 g_kh[(size_t)BH_NUM * S_LEN * HD];
__device__ __nv_bfloat16 g_kl[(size_t)BH_NUM * S_LEN * HD];
__device__ __nv_bfloat16 g_vh[(size_t)BH_NUM * S_LEN * HD];
__device__ __nv_bfloat16 g_vl[(size_t)BH_NUM * S_LEN * HD];
__device__ float4 g_rope[(size_t)S_LEN * 64];                  // (c0,s0,c1,s1) per (s, hd/2)

// ---------------------------------------------------------------------------
// Helpers (plain sm_103-legal: cp.async, ldmatrix, mma.sync bf16)
// ---------------------------------------------------------------------------
__device__ __forceinline__ uint32_t smem_u32(const void* p) {
    uint32_t a;
    asm("{ .reg .u64 t; cvta.to.shared.u64 t, %1; cvt.u32.u64 %0, t; }"
        : "=r"(a) : "l"(p));
    return a;
}

__device__ __forceinline__ void cp16(uint32_t sm_dst, const void* g_src) {
    asm volatile("cp.async.cg.shared.global [%0], [%1], 16;"
                 :: "r"(sm_dst), "l"(g_src));
}
#define CP_COMMIT() asm volatile("cp.async.commit_group;" ::: "memory")
#define CP_WAIT1()  asm volatile("cp.async.wait_group 1;" ::: "memory")
#define CP_WAIT0()  asm volatile("cp.async.wait_group 0;" ::: "memory")

__device__ __forceinline__ void ldsm4(uint32_t* r, uint32_t addr) {
    asm volatile("ldmatrix.sync.aligned.m8n8.x4.shared.b16 {%0,%1,%2,%3}, [%4];"
                 : "=r"(r[0]), "=r"(r[1]), "=r"(r[2]), "=r"(r[3]) : "r"(addr));
}
__device__ __forceinline__ void ldsm4t(uint32_t* r, uint32_t addr) {
    asm volatile("ldmatrix.sync.aligned.m8n8.x4.trans.shared.b16 {%0,%1,%2,%3}, [%4];"
                 : "=r"(r[0]), "=r"(r[1]), "=r"(r[2]), "=r"(r[3]) : "r"(addr));
}

__device__ __forceinline__ void mma_bf16(float* d, const uint32_t* a,
                                         const uint32_t* b) {
    asm volatile(
        "mma.sync.aligned.m16n8k16.row.col.f32.bf16.bf16.f32 "
        "{%0,%1,%2,%3}, {%4,%5,%6,%7}, {%8,%9}, {%0,%1,%2,%3};"
        : "+f"(d[0]), "+f"(d[1]), "+f"(d[2]), "+f"(d[3])
        : "r"(a[0]), "r"(a[1]), "r"(a[2]), "r"(a[3]), "r"(b[0]), "r"(b[1]));
}

// ---------------------------------------------------------------------------
// RoPE table: g_rope[s*64 + p] = (cos(a0), sin(a0), cos(a1), sin(a1)) for
// hd = 2p, 2p+1, freq index t = hd & 63 (exact Round-2/5 math).
// ---------------------------------------------------------------------------
__global__ void ropetab_kernel(float4* __restrict__ T)
{
    int idx = blockIdx.x * 256 + threadIdx.x;     // < 2048*64
    int p = idx & 63, s = idx >> 6;
    int t0 = (2 * p) & 63;
    int t1 = (2 * p + 1) & 63;
    const float nlog = -9.210340372f;             // -ln(10000)
    float f0 = __expf(nlog * (float)t0 * (1.0f / 64.0f));
    float f1 = __expf(nlog * (float)t1 * (1.0f / 64.0f));
    float c0, s0, c1, s1;
    sincosf((float)s * f0, &s0, &c0);
    sincosf((float)s * f1, &s1, &c1);
    T[idx] = make_float4(c0, s0, c1, s1);
}

// ---------------------------------------------------------------------------
// bf16-split GEMM v2: CTA tile 128x256, BK=32, 8 warps (2M x 4N, warp 64x64),
// 3-stage cp.async ring, 80B smem row stride. 3-term split, fp32 accum.
// qkv_mode=1: fused RoPE(table)/scale/bf16-split epilogue to [BH,S,HD].
// ---------------------------------------------------------------------------
#define MG_BK 32
#define MG_NC (KDIM / MG_BK)        // 64
#define MGA_BYTES (128 * 80)        // 10240  (A hi or lo)
#define MGB_BYTES (256 * 80)        // 20480  (B hi or lo)
#define STAGE_B (2 * MGA_BYTES + 2 * MGB_BYTES)   // 61440
#define MG_SMEM (3 * STAGE_B)       // 184320

__device__ __forceinline__ void mg_load(
    uint32_t st, const __nv_bfloat16* Ah, const __nv_bfloat16* Al,
    const __nv_bfloat16* Bh, const __nv_bfloat16* Bl,
    int m0, int n0, int k0, int tid)
{
#pragma unroll
    for (int i = 0; i < 2; i++) {                 // A: 128 rows x 4 chunks
        int idx = tid + i * 256;                  // 0..511
        int r = idx >> 2, ch = idx & 3;
        uint32_t off = (uint32_t)r * 80 + ch * 16;
        size_t ga = (size_t)(m0 + r) * KDIM + k0 + ch * 8;
        cp16(st + off,             Ah + ga);
        cp16(st + MGA_BYTES + off, Al + ga);
    }
#pragma unroll
    for (int i = 0; i < 4; i++) {                 // B: 256 rows x 4 chunks
        int idx = tid + i * 256;                  // 0..1023
        int r = idx >> 2, ch = idx & 3;
        uint32_t off = (uint32_t)r * 80 + ch * 16;
        size_t gb = (size_t)(n0 + r) * KDIM + k0 + ch * 8;
        cp16(st + 2 * MGA_BYTES + off,             Bh + gb);
        cp16(st + 2 * MGA_BYTES + MGB_BYTES + off, Bl + gb);
    }
}

__global__ __launch_bounds__(256, 1)
void mma_gemm_kernel(const __nv_bfloat16* __restrict__ Ah,
                     const __nv_bfloat16* __restrict__ Al,
                     const __nv_bfloat16* __restrict__ WtH,
                     const __nv_bfloat16* __restrict__ WtL,
                     const float4* __restrict__ Rope,
                     __nv_bfloat16* H0, __nv_bfloat16* L0,
                     __nv_bfloat16* H1, __nv_bfloat16* L1,
                     __nv_bfloat16* H2, __nv_bfloat16* L2,
                     float* Cf,
                     int wbase, int qkv_mode)
{
    extern __shared__ __align__(256) char smem[];
    uint32_t sb = smem_u32(smem);
    int tid = threadIdx.x;
    int wid = tid >> 5, lane = tid & 31;
    int z = blockIdx.z;

    const __nv_bfloat16* Bh = WtH + (size_t)(wbase + z) * D_DIM * KDIM;
    const __nv_bfloat16* Bl = WtL + (size_t)(wbase + z) * D_DIM * KDIM;
    int m0 = blockIdx.y * 128;
    int n0 = blockIdx.x * 256;

    int wm = wid & 1;              // 2 warps along M (64 rows each)
    int wn = wid >> 1;             // 4 warps along N (64 cols each)

    float acc[4][8][4];
#pragma unroll
    for (int i = 0; i < 4; i++)
#pragma unroll
        for (int j = 0; j < 8; j++)
#pragma unroll
            for (int t = 0; t < 4; t++) acc[i][j][t] = 0.f;

    mg_load(sb,           Ah, Al, Bh, Bl, m0, n0, 0,     tid); CP_COMMIT();
    mg_load(sb + STAGE_B, Ah, Al, Bh, Bl, m0, n0, MG_BK, tid); CP_COMMIT();

    int a_row  = wm * 64 + (lane & 15);
    uint32_t a_koff = ((lane >> 4) & 1) * 16;
    int b_row  = wn * 64 + (lane & 7) + (((lane >> 4) & 1) << 3);
    uint32_t b_koff = ((lane >> 3) & 1) * 16;

    for (int c = 0; c < MG_NC; c++) {
        if (c + 2 >= MG_NC) { CP_WAIT0(); } else { CP_WAIT1(); }
        __syncthreads();
        uint32_t u = sb + (uint32_t)(c % 3) * STAGE_B;
        uint32_t uAh = u, uAl = u + MGA_BYTES;
        uint32_t uBh = u + 2 * MGA_BYTES, uBl = uBh + MGB_BYTES;

#pragma unroll
        for (int ks = 0; ks < 2; ks++) {
            uint32_t kb = ks * 32;
            uint32_t bhf[4][4], blf[4][4];
#pragma unroll
            for (int j = 0; j < 4; j++) {
                uint32_t bo = (uint32_t)(b_row + j * 16) * 80 + b_koff + kb;
                ldsm4(bhf[j], uBh + bo);
                ldsm4(blf[j], uBl + bo);
            }
#pragma unroll
            for (int i = 0; i < 4; i++) {
                uint32_t ahf[4], alf[4];
                uint32_t ao = (uint32_t)(a_row + i * 16) * 80 + a_koff + kb;
                ldsm4(ahf, uAh + ao);
                ldsm4(alf, uAl + ao);
#pragma unroll
                for (int j = 0; j < 4; j++) {
                    mma_bf16(acc[i][2 * j],     ahf, &bhf[j][0]);
                    mma_bf16(acc[i][2 * j + 1], ahf, &bhf[j][2]);
                    mma_bf16(acc[i][2 * j],     ahf, &blf[j][0]);
                    mma_bf16(acc[i][2 * j + 1], ahf, &blf[j][2]);
                    mma_bf16(acc[i][2 * j],     alf, &bhf[j][0]);
                    mma_bf16(acc[i][2 * j + 1], alf, &bhf[j][2]);
                }
            }
        }

        if (c + 2 < MG_NC) {
            mg_load(sb + (uint32_t)((c + 2) % 3) * STAGE_B,
                    Ah, Al, Bh, Bl, m0, n0, (c + 2) * MG_BK, tid);
            CP_COMMIT();
        }
    }

    int r0 = m0 + wm * 64 + (lane >> 2);
    int c0 = n0 + wn * 64 + (lane & 3) * 2;

    if (!qkv_mode) {
#pragma unroll
        for (int i = 0; i < 4; i++) {
#pragma unroll
            for (int j = 0; j < 8; j++) {
                int gn = c0 + j * 8;
#pragma unroll
                for (int half = 0; half < 2; half++) {
                    int gm = r0 + i * 16 + half * 8;
                    *(float2*)&Cf[(size_t)gm * D_DIM + gn] =
                        make_float2(acc[i][j][2 * half], acc[i][j][2 * half + 1]);
                }
            }
        }
    } else {
        __nv_bfloat16* HZ = (z == 0) ? H0 : ((z == 1) ? H1 : H2);
        __nv_bfloat16* LZ = (z == 0) ? L0 : ((z == 1) ? L1 : L2);
        const float qscale = 0.08838834764831845f;  // 1/sqrt(128)
#pragma unroll
        for (int j = 0; j < 8; j++) {
            int gn = c0 + j * 8;
            int hd = gn & 127;
            int h  = gn >> 7;
            int pidx = hd >> 1;
#pragma unroll
            for (int i = 0; i < 4; i++) {
#pragma unroll
                for (int half = 0; half < 2; half++) {
                    int gm = r0 + i * 16 + half * 8;
                    int b = gm >> 11, s = gm & 2047;
                    float x0 = acc[i][j][2 * half];
                    float x1 = acc[i][j][2 * half + 1];
                    float y0 = x0, y1 = x1;
                    if (z < 2) {
                        float4 t = Rope[s * 64 + pidx];
                        y0 = x0 * t.x - x1 * t.y;   // even: x*cos - x_odd*sin
                        y1 = x1 * t.z + x0 * t.w;   // odd:  x*cos + x_even*sin
                        if (z == 0) { y0 *= qscale; y1 *= qscale; }
                    }
                    __nv_bfloat16 hh0 = __float2bfloat16(y0);
                    __nv_bfloat16 hh1 = __float2bfloat16(y1);
                    __nv_bfloat16 ll0 = __float2bfloat16(y0 - __bfloat162float(hh0));
                    __nv_bfloat16 ll1 = __float2bfloat16(y1 - __bfloat162float(hh1));
                    size_t off = (((size_t)(b * H_NUM + h)) * S_LEN + s) * HD + hd;
                    *(__nv_bfloat162*)(HZ + off) = __nv_bfloat162(hh0, hh1);
                    *(__nv_bfloat162*)(LZ + off) = __nv_bfloat162(ll0, ll1);
                }
            }
        }
    }
}

// ---------------------------------------------------------------------------
// fp32 -> (hi, lo) bf16 split, 4 elems/thread (x input only)
// ---------------------------------------------------------------------------
__global__ void split_kernel(const float* __restrict__ X,
                             __nv_bfloat16* __restrict__ Hh,
                             __nv_bfloat16* __restrict__ Ll)
{
    size_t i = ((size_t)blockIdx.x * blockDim.x + threadIdx.x) * 4;
    float4 v = *(const float4*)(X + i);
    __nv_bfloat16 h0 = __float2bfloat16(v.x);
    __nv_bfloat16 h1 = __float2bfloat16(v.y);
    __nv_bfloat16 h2 = __float2bfloat16(v.z);
    __nv_bfloat16 h3 = __float2bfloat16(v.w);
    __nv_bfloat16 l0 = __float2bfloat16(v.x - __bfloat162float(h0));
    __nv_bfloat16 l1 = __float2bfloat16(v.y - __bfloat162float(h1));
    __nv_bfloat16 l2 = __float2bfloat16(v.z - __bfloat162float(h2));
    __nv_bfloat16 l3 = __float2bfloat16(v.w - __bfloat162float(h3));
    __nv_bfloat162* hp = (__nv_bfloat162*)(Hh + i);
    __nv_bfloat162* lp = (__nv_bfloat162*)(Ll + i);
    hp[0] = __nv_bfloat162(h0, h1); hp[1] = __nv_bfloat162(h2, h3);
    lp[0] = __nv_bfloat162(l0, l1); lp[1] = __nv_bfloat162(l2, l3);
}

// ---------------------------------------------------------------------------
// Weight transpose + split (unchanged)
// ---------------------------------------------------------------------------
__global__ void wtrans_kernel(const float* __restrict__ W0, const float* __restrict__ W1,
                              const float* __restrict__ W2, const float* __restrict__ W3,
                              __nv_bfloat16* __restrict__ TH,
                              __nv_bfloat16* __restrict__ TL)
{
    __shared__ float t[32][33];
    int z = blockIdx.z;
    const float* W = (z == 0) ? W0 : (z == 1 ? W1 : (z == 2 ? W2 : W3));
    __nv_bfloat16* th = TH + (size_t)z * D_DIM * KDIM;
    __nv_bfloat16* tl = TL + (size_t)z * D_DIM * KDIM;
    int k0 = blockIdx.y * 32, n0 = blockIdx.x * 32;
    int tx = threadIdx.x, ty = threadIdx.y;
#pragma unroll
    for (int i = 0; i < 4; i++)
        t[ty + 8 * i][tx] = W[(size_t)(k0 + ty + 8 * i) * D_DIM + n0 + tx];
    __syncthreads();
#pragma unroll
    for (int i = 0; i < 4; i++) {
        float v = t[tx][ty + 8 * i];
        __nv_bfloat16 h = __float2bfloat16(v);
        __nv_bfloat16 l = __float2bfloat16(v - __bfloat162float(h));
        size_t o = (size_t)(n0 + ty + 8 * i) * KDIM + k0 + tx;
        th[o] = h;
        tl[o] = l;
    }
}

// ---------------------------------------------------------------------------
// Tensor-core flash attention (bf16 split, fp32 softmax), causal.
// UNCHANGED from Round 6 (passed; 352us, tensor=50.9%).
// ---------------------------------------------------------------------------
#define FR_STRIDE 272
#define FQ_BYTES  (128 * FR_STRIDE)
#define FKV_MAT   (64 * FR_STRIDE)
#define FSTAGE    (4 * FKV_MAT)
#define FA2_SMEM  (2 * FQ_BYTES + 2 * FSTAGE)

__device__ __forceinline__ void fa_load_kv(
    uint32_t st, const __nv_bfloat16* KH, const __nv_bfloat16* KL,
    const __nv_bfloat16* VH, const __nv_bfloat16* VL,
    int bh, int kb, int tid)
{
#pragma unroll
    for (int i = 0; i < 4; i++) {
        int idx = tid + i * 256;
        int r = idx >> 4, ch = idx & 15;
        uint32_t off = (uint32_t)r * FR_STRIDE + ch * 16;
        size_t g = ((size_t)bh * S_LEN + kb * 64 + r) * HD + ch * 8;
        cp16(st + off,               KH + g);
        cp16(st + FKV_MAT + off,     KL + g);
        cp16(st + 2 * FKV_MAT + off, VH + g);
        cp16(st + 3 * FKV_MAT + off, VL + g);
    }
}

__global__ __launch_bounds__(256, 1)
void flash_mma_kernel(const __nv_bfloat16* __restrict__ QH,
                      const __nv_bfloat16* __restrict__ QL,
                      const __nv_bfloat16* __restrict__ KH,
                      const __nv_bfloat16* __restrict__ KL,
                      const __nv_bfloat16* __restrict__ VH,
                      const __nv_bfloat16* __restrict__ VL,
                      __nv_bfloat16* __restrict__ AH,
                      __nv_bfloat16* __restrict__ AL)
{
    extern __shared__ __align__(256) char smem[];
    uint32_t sb = smem_u32(smem);
    const uint32_t uQH = sb, uQL = sb + FQ_BYTES;
    const uint32_t uST0 = sb + 2 * FQ_BYTES;

    int tid = threadIdx.x;
    int wid = tid >> 5, lane = tid & 31;
    int qb = 15 - blockIdx.x;
    int bh = blockIdx.y;
    int nkb = 2 * qb + 2;

#pragma unroll
    for (int i = 0; i < 8; i++) {
        int idx = tid + i * 256;
        int r = idx >> 4, ch = idx & 15;
        uint32_t off = (uint32_t)r * FR_STRIDE + ch * 16;
        size_t g = ((size_t)bh * S_LEN + qb * 128 + r) * HD + ch * 8;
        cp16(uQH + off, QH + g);
        cp16(uQL + off, QL + g);
    }
    CP_COMMIT();
    fa_load_kv(uST0, KH, KL, VH, VL, bh, 0, tid); CP_COMMIT();
    if (nkb > 1) { fa_load_kv(uST0 + FSTAGE, KH, KL, VH, VL, bh, 1, tid); CP_COMMIT(); }

    float accO[16][4];
#pragma unroll
    for (int j = 0; j < 16; j++)
#pragma unroll
        for (int t = 0; t < 4; t++) accO[j][t] = 0.f;
    float m0v = -INFINITY, m1v = -INFINITY, l0v = 0.f, l1v = 0.f;

    uint32_t q_ao = (uint32_t)(wid * 16 + (lane & 15)) * FR_STRIDE + ((lane >> 4) & 1) * 16;
    uint32_t k_bo = (uint32_t)((lane & 7) + (((lane >> 4) & 1) << 3)) * FR_STRIDE
                    + ((lane >> 3) & 1) * 16;
    uint32_t v_to = (uint32_t)(lane & 15) * FR_STRIDE + ((lane >> 4) & 1) * 16;

    if (nkb > 1) { CP_WAIT1(); } else { CP_WAIT0(); }
    __syncthreads();

    for (int kb = 0; kb < nkb; kb++) {
        uint32_t st = uST0 + (uint32_t)(kb & 1) * FSTAGE;
        uint32_t stKH = st, stKL = st + FKV_MAT;
        uint32_t stVH = st + 2 * FKV_MAT, stVL = st + 3 * FKV_MAT;

        float accS[8][4];
#pragma unroll
        for (int j = 0; j < 8; j++)
#pragma unroll
            for (int t = 0; t < 4; t++) accS[j][t] = 0.f;

#pragma unroll
        for (int ks = 0; ks < 8; ks++) {
            uint32_t qh[4], ql[4];
            ldsm4(qh, uQH + q_ao + ks * 32);
            ldsm4(ql, uQL + q_ao + ks * 32);
#pragma unroll
            for (int j = 0; j < 4; j++) {
                uint32_t kh[4], kl[4];
                uint32_t bo = k_bo + (uint32_t)j * 16 * FR_STRIDE + ks * 32;
                ldsm4(kh, stKH + bo);
                ldsm4(kl, stKL + bo);
                mma_bf16(accS[2 * j],     qh, &kh[0]);
                mma_bf16(accS[2 * j + 1], qh, &kh[2]);
                mma_bf16(accS[2 * j],     qh, &kl[0]);
                mma_bf16(accS[2 * j + 1], qh, &kl[2]);
                mma_bf16(accS[2 * j],     ql, &kh[0]);
                mma_bf16(accS[2 * j + 1], ql, &kh[2]);
            }
        }

        if (kb >= 2 * qb) {
            int grow = qb * 128 + wid * 16 + (lane >> 2);
#pragma unroll
            for (int j = 0; j < 8; j++) {
                int col = kb * 64 + j * 8 + ((lane & 3) << 1);
                if (col     > grow)     accS[j][0] = -INFINITY;
                if (col + 1 > grow)     accS[j][1] = -INFINITY;
                if (col     > grow + 8) accS[j][2] = -INFINITY;
                if (col + 1 > grow + 8) accS[j][3] = -INFINITY;
            }
        }

        float rm0 = -INFINITY, rm1 = -INFINITY;
#pragma unroll
        for (int j = 0; j < 8; j++) {
            rm0 = fmaxf(rm0, fmaxf(accS[j][0], accS[j][1]));
            rm1 = fmaxf(rm1, fmaxf(accS[j][2], accS[j][3]));
        }
        rm0 = fmaxf(rm0, __shfl_xor_sync(0xffffffffu, rm0, 1));
        rm0 = fmaxf(rm0, __shfl_xor_sync(0xffffffffu, rm0, 2));
        rm1 = fmaxf(rm1, __shfl_xor_sync(0xffffffffu, rm1, 1));
        rm1 = fmaxf(rm1, __shfl_xor_sync(0xffffffffu, rm1, 2));

        float mn0 = fmaxf(m0v, rm0), mn1 = fmaxf(m1v, rm1);
        float al0 = __expf(m0v - mn0), al1 = __expf(m1v - mn1);
        m0v = mn0; m1v = mn1;

        float rs0 = 0.f, rs1 = 0.f;
#pragma unroll
        for (int j = 0; j < 8; j++) {
            accS[j][0] = __expf(accS[j][0] - mn0);
            accS[j][1] = __expf(accS[j][1] - mn0);
            accS[j][2] = __expf(accS[j][2] - mn1);
            accS[j][3] = __expf(accS[j][3] - mn1);
            rs0 += accS[j][0] + accS[j][1];
            rs1 += accS[j][2] + accS[j][3];
        }
        rs0 += __shfl_xor_sync(0xffffffffu, rs0, 1);
        rs0 += __shfl_xor_sync(0xffffffffu, rs0, 2);
        rs1 += __shfl_xor_sync(0xffffffffu, rs1, 1);
        rs1 += __shfl_xor_sync(0xffffffffu, rs1, 2);
        l0v = l0v * al0 + rs0;
        l1v = l1v * al1 + rs1;

#pragma unroll
        for (int j = 0; j < 16; j++) {
            accO[j][0] *= al0; accO[j][1] *= al0;
            accO[j][2] *= al1; accO[j][3] *= al1;
        }

        uint32_t pa_h[8][2], pa_l[8][2];
#pragma unroll
        for (int j = 0; j < 8; j++) {
            __nv_bfloat16 h0 = __float2bfloat16(accS[j][0]);
            __nv_bfloat16 h1 = __float2bfloat16(accS[j][1]);
            __nv_bfloat16 h2 = __float2bfloat16(accS[j][2]);
            __nv_bfloat16 h3 = __float2bfloat16(accS[j][3]);
            __nv_bfloat16 e0 = __float2bfloat16(accS[j][0] - __bfloat162float(h0));
            __nv_bfloat16 e1 = __float2bfloat16(accS[j][1] - __bfloat162float(h1));
            __nv_bfloat16 e2 = __float2bfloat16(accS[j][2] - __bfloat162float(h2));
            __nv_bfloat16 e3 = __float2bfloat16(accS[j][3] - __bfloat162float(h3));
            pa_h[j][0] = ((uint32_t)__bfloat16_as_ushort(h1) << 16) | __bfloat16_as_ushort(h0);
            pa_h[j][1] = ((uint32_t)__bfloat16_as_ushort(h3) << 16) | __bfloat16_as_ushort(h2);
            pa_l[j][0] = ((uint32_t)__bfloat16_as_ushort(e1) << 16) | __bfloat16_as_ushort(e0);
            pa_l[j][1] = ((uint32_t)__bfloat16_as_ushort(e3) << 16) | __bfloat16_as_ushort(e2);
        }

#pragma unroll
        for (int ks = 0; ks < 4; ks++) {
            uint32_t ah4[4] = { pa_h[2 * ks][0], pa_h[2 * ks][1],
                                pa_h[2 * ks + 1][0], pa_h[2 * ks + 1][1] };
            uint32_t al4[4] = { pa_l[2 * ks][0], pa_l[2 * ks][1],
                                pa_l[2 * ks + 1][0], pa_l[2 * ks + 1][1] };
#pragma unroll
            for (int j2 = 0; j2 < 8; j2++) {
                uint32_t vh[4], vl[4];
                uint32_t vo = v_to + (uint32_t)ks * 16 * FR_STRIDE + j2 * 32;
                ldsm4t(vh, stVH + vo);
                ldsm4t(vl, stVL + vo);
                mma_bf16(accO[2 * j2],     ah4, &vh[0]);
                mma_bf16(accO[2 * j2 + 1], ah4, &vh[2]);
                mma_bf16(accO[2 * j2],     ah4, &vl[0]);
                mma_bf16(accO[2 * j2 + 1], ah4, &vl[2]);
                mma_bf16(accO[2 * j2],     al4, &vh[0]);
                mma_bf16(accO[2 * j2 + 1], al4, &vh[2]);
            }
        }

        __syncthreads();
        if (kb + 2 < nkb) {
            fa_load_kv(st, KH, KL, VH, VL, bh, kb + 2, tid);
            CP_COMMIT();
        }
        if (kb + 1 < nkb) {
            if (kb + 2 < nkb) { CP_WAIT1(); } else { CP_WAIT0(); }
            __syncthreads();
        }
    }

    int b = bh >> 4, h = bh & 15;
    int srow = qb * 128 + wid * 16 + (lane >> 2);
    float inv0 = 1.0f / l0v, inv1 = 1.0f / l1v;
#pragma unroll
    for (int j = 0; j < 16; j++) {
        int col = h * HD + j * 8 + ((lane & 3) << 1);
        size_t o0 = ((size_t)b * S_LEN + srow) * D_DIM + col;
        size_t o1 = ((size_t)b * S_LEN + srow + 8) * D_DIM + col;
        float v00 = accO[j][0] * inv0, v01 = accO[j][1] * inv0;
        float v10 = accO[j][2] * inv1, v11 = accO[j][3] * inv1;
        __nv_bfloat16 h00 = __float2bfloat16(v00);
        __nv_bfloat16 h01 = __float2bfloat16(v01);
        __nv_bfloat16 h10 = __float2bfloat16(v10);
        __nv_bfloat16 h11 = __float2bfloat16(v11);
        __nv_bfloat16 l00 = __float2bfloat16(v00 - __bfloat162float(h00));
        __nv_bfloat16 l01 = __float2bfloat16(v01 - __bfloat162float(h01));
        __nv_bfloat16 l10 = __float2bfloat16(v10 - __bfloat162float(h10));
        __nv_bfloat16 l11 = __float2bfloat16(v11 - __bfloat162float(h11));
        *(__nv_bfloat162*)(AH + o0) = __nv_bfloat162(h00, h01);
        *(__nv_bfloat162*)(AL + o0) = __nv_bfloat162(l00, l01);
        *(__nv_bfloat162*)(AH + o1) = __nv_bfloat162(h10, h11);
        *(__nv_bfloat162*)(AL + o1) = __nv_bfloat162(l10, l11);
    }
}

// ---------------------------------------------------------------------------
extern "C" void kernel_launch(void* const* d_in, const int* in_sizes, int n_in,
                              void* d_out, int out_size)
{
    const float* x  = (const float*)d_in[0];
    const float* Wq = (const float*)d_in[1];
    const float* Wk = (const float*)d_in[2];
    const float* Wv = (const float*)d_in[3];
    const float* Wo = (const float*)d_in[4];
    float* out = (float*)d_out;

    __nv_bfloat16 *pah, *pal, *pwh, *pwl;
    __nv_bfloat16 *pqh, *pql, *pkh, *pkl, *pvh, *pvl;
    float4* prt;
    cudaGetSymbolAddress((void**)&pah, g_ah);
    cudaGetSymbolAddress((void**)&pal, g_al);
    cudaGetSymbolAddress((void**)&pwh, g_wth);
    cudaGetSymbolAddress((void**)&pwl, g_wtl);
    cudaGetSymbolAddress((void**)&pqh, g_qh);
    cudaGetSymbolAddress((void**)&pql, g_ql);
    cudaGetSymbolAddress((void**)&pkh, g_kh);
    cudaGetSymbolAddress((void**)&pkl, g_kl);
    cudaGetSymbolAddress((void**)&pvh, g_vh);
    cudaGetSymbolAddress((void**)&pvl, g_vl);
    cudaGetSymbolAddress((void**)&prt, g_rope);

    cudaFuncSetAttribute(mma_gemm_kernel,
                         cudaFuncAttributeMaxDynamicSharedMemorySize, MG_SMEM);
    cudaFuncSetAttribute(flash_mma_kernel,
                         cudaFuncAttributeMaxDynamicSharedMemorySize, FA2_SMEM);

    // 0) bf16 split of x
    split_kernel<<<(M_ROWS * KDIM / 4) / 256, 256>>>(x, pah, pal);

    // 1) weight transpose + split
    wtrans_kernel<<<dim3(D_DIM / 32, KDIM / 32, 4), dim3(32, 8)>>>(
        Wq, Wk, Wv, Wo, pwh, pwl);

    // 2) RoPE cos/sin table
    ropetab_kernel<<<(S_LEN * 64) / 256, 256>>>(prt);

    // 3) QKV projections + fused RoPE(table)/scale/bf16-split epilogue
    mma_gemm_kernel<<<dim3(D_DIM / 256, M_ROWS / 128, 3), 256, MG_SMEM>>>(
        pah, pal, pwh, pwl, prt,
        pqh, pql, pkh, pkl, pvh, pvl, (float*)nullptr, 0, 1);

    // 4) tensor-core causal flash attention (writes bf16 hi/lo attn-out)
    flash_mma_kernel<<<dim3(S_LEN / 128, BH_NUM), 256, FA2_SMEM>>>(
        pqh, pql, pkh, pkl, pvh, pvl, pah, pal);

    // 5) O projection -> d_out (fp32)
    mma_gemm_kernel<<<dim3(D_DIM / 256, M_ROWS / 128, 1), 256, MG_SMEM>>>(
        pah, pal, pwh, pwl, prt,
        (__nv_bfloat16*)nullptr, (__nv_bfloat16*)nullptr,
        (__nv_bfloat16*)nullptr, (__nv_bfloat16*)nullptr,
        (__nv_bfloat16*)nullptr, (__nv_bfloat16*)nullptr,
        out, 3, 0);
}

// round 12
// speedup vs baseline: 1.1391x; 1.0508x over previous
#include <cuda_runtime.h>
#include <cuda_bf16.h>
#include <math.h>
#include <stdint.h>

#define S_LEN 2048
#define D_DIM 2048
#define H_NUM 16
#define HD    128
#define B_NUM 2
#define M_ROWS (B_NUM * S_LEN)   // 4096
#define KDIM  2048
#define BH_NUM (B_NUM * H_NUM)   // 32

// ---------------------------------------------------------------------------
// Scratch (device globals: no allocation allowed)
// ---------------------------------------------------------------------------
__device__ __nv_bfloat16 g_ah[(size_t)M_ROWS * KDIM];          // A hi (x, then attn-out)
__device__ __nv_bfloat16 g_al[(size_t)M_ROWS * KDIM];          // A lo
__device__ __nv_bfloat16 g_wth[(size_t)4 * D_DIM * KDIM];      // W^T hi
__device__ __nv_bfloat16 g_wtl[(size_t)4 * D_DIM * KDIM];      // W^T lo
__device__ __nv_bfloat16 g_qh[(size_t)BH_NUM * S_LEN * HD];
__device__ __nv_bfloat16 g_ql[(size_t)BH_NUM * S_LEN * HD];
__device__ __nv_bfloat16 g_kh[(size_t)BH_NUM * S_LEN * HD];
__device__ __nv_bfloat16 g_kl[(size_t)BH_NUM * S_LEN * HD];
__device__ __nv_bfloat16 g_vh[(size_t)BH_NUM * S_LEN * HD];
__device__ __nv_bfloat16 g_vl[(size_t)BH_NUM * S_LEN * HD];
__device__ float4 g_rope[(size_t)S_LEN * 64];                  // (c0,s0,c1,s1) per (s, hd/2)

// ---------------------------------------------------------------------------
// Helpers (plain sm_103-legal: cp.async, ldmatrix, mma.sync bf16)
// ---------------------------------------------------------------------------
__device__ __forceinline__ uint32_t smem_u32(const void* p) {
    uint32_t a;
    asm("{ .reg .u64 t; cvta.to.shared.u64 t, %1; cvt.u32.u64 %0, t; }"
        : "=r"(a) : "l"(p));
    return a;
}

__device__ __forceinline__ void cp16(uint32_t sm_dst, const void* g_src) {
    asm volatile("cp.async.cg.shared.global [%0], [%1], 16;"
                 :: "r"(sm_dst), "l"(g_src));
}
#define CP_COMMIT() asm volatile("cp.async.commit_group;" ::: "memory")
#define CP_WAIT1()  asm volatile("cp.async.wait_group 1;" ::: "memory")
#define CP_WAIT0()  asm volatile("cp.async.wait_group 0;" ::: "memory")

__device__ __forceinline__ void ldsm4(uint32_t* r, uint32_t addr) {
    asm volatile("ldmatrix.sync.aligned.m8n8.x4.shared.b16 {%0,%1,%2,%3}, [%4];"
                 : "=r"(r[0]), "=r"(r[1]), "=r"(r[2]), "=r"(r[3]) : "r"(addr));
}
__device__ __forceinline__ void ldsm4t(uint32_t* r, uint32_t addr) {
    asm volatile("ldmatrix.sync.aligned.m8n8.x4.trans.shared.b16 {%0,%1,%2,%3}, [%4];"
                 : "=r"(r[0]), "=r"(r[1]), "=r"(r[2]), "=r"(r[3]) : "r"(addr));
}

__device__ __forceinline__ void mma_bf16(float* d, const uint32_t* a,
                                         const uint32_t* b) {
    asm volatile(
        "mma.sync.aligned.m16n8k16.row.col.f32.bf16.bf16.f32 "
        "{%0,%1,%2,%3}, {%4,%5,%6,%7}, {%8,%9}, {%0,%1,%2,%3};"
        : "+f"(d[0]), "+f"(d[1]), "+f"(d[2]), "+f"(d[3])
        : "r"(a[0]), "r"(a[1]), "r"(a[2]), "r"(a[3]), "r"(b[0]), "r"(b[1]));
}

// ---------------------------------------------------------------------------
// RoPE table: g_rope[s*64 + p] = (cos(a0), sin(a0), cos(a1), sin(a1)) for
// hd = 2p, 2p+1, freq index t = hd & 63 (exact Round-2/5 math).
// ---------------------------------------------------------------------------
__global__ void ropetab_kernel(float4* __restrict__ T)
{
    int idx = blockIdx.x * 256 + threadIdx.x;     // < 2048*64
    int p = idx & 63, s = idx >> 6;
    int t0 = (2 * p) & 63;
    int t1 = (2 * p + 1) & 63;
    const float nlog = -9.210340372f;             // -ln(10000)
    float f0 = __expf(nlog * (float)t0 * (1.0f / 64.0f));
    float f1 = __expf(nlog * (float)t1 * (1.0f / 64.0f));
    float c0, s0, c1, s1;
    sincosf((float)s * f0, &s0, &c0);
    sincosf((float)s * f1, &s1, &c1);
    T[idx] = make_float4(c0, s0, c1, s1);
}

// ---------------------------------------------------------------------------
// bf16-split GEMM v3: CTA tile 128x256, BK=32, 512 threads / 16 warps
// (4M x 4N, warp tile 32x64) for 4 warps/SMSP latency hiding.
// 3-stage cp.async ring, 80B smem row stride, 3-term split, fp32 accum.
// qkv_mode=1: fused RoPE(table)/scale/bf16-split epilogue to [BH,S,HD].
// ---------------------------------------------------------------------------
#define MG_BK 32
#define MG_NC (KDIM / MG_BK)        // 64
#define MGA_BYTES (128 * 80)        // 10240  (A hi or lo)
#define MGB_BYTES (256 * 80)        // 20480  (B hi or lo)
#define STAGE_B (2 * MGA_BYTES + 2 * MGB_BYTES)   // 61440
#define MG_SMEM (3 * STAGE_B)       // 184320
#define MG_THREADS 512

__device__ __forceinline__ void mg_load(
    uint32_t st, const __nv_bfloat16* Ah, const __nv_bfloat16* Al,
    const __nv_bfloat16* Bh, const __nv_bfloat16* Bl,
    int m0, int n0, int k0, int tid)
{
    {                                              // A: 128 rows x 4 chunks = 512
        int r = tid >> 2, ch = tid & 3;
        uint32_t off = (uint32_t)r * 80 + ch * 16;
        size_t ga = (size_t)(m0 + r) * KDIM + k0 + ch * 8;
        cp16(st + off,             Ah + ga);
        cp16(st + MGA_BYTES + off, Al + ga);
    }
#pragma unroll
    for (int i = 0; i < 2; i++) {                  // B: 256 rows x 4 chunks = 1024
        int idx = tid + i * MG_THREADS;
        int r = idx >> 2, ch = idx & 3;
        uint32_t off = (uint32_t)r * 80 + ch * 16;
        size_t gb = (size_t)(n0 + r) * KDIM + k0 + ch * 8;
        cp16(st + 2 * MGA_BYTES + off,             Bh + gb);
        cp16(st + 2 * MGA_BYTES + MGB_BYTES + off, Bl + gb);
    }
}

__global__ __launch_bounds__(MG_THREADS, 1)
void mma_gemm_kernel(const __nv_bfloat16* __restrict__ Ah,
                     const __nv_bfloat16* __restrict__ Al,
                     const __nv_bfloat16* __restrict__ WtH,
                     const __nv_bfloat16* __restrict__ WtL,
                     const float4* __restrict__ Rope,
                     __nv_bfloat16* H0, __nv_bfloat16* L0,
                     __nv_bfloat16* H1, __nv_bfloat16* L1,
                     __nv_bfloat16* H2, __nv_bfloat16* L2,
                     float* Cf,
                     int wbase, int qkv_mode)
{
    extern __shared__ __align__(256) char smem[];
    uint32_t sb = smem_u32(smem);
    int tid = threadIdx.x;
    int wid = tid >> 5, lane = tid & 31;
    int z = blockIdx.z;

    const __nv_bfloat16* Bh = WtH + (size_t)(wbase + z) * D_DIM * KDIM;
    const __nv_bfloat16* Bl = WtL + (size_t)(wbase + z) * D_DIM * KDIM;
    int m0 = blockIdx.y * 128;
    int n0 = blockIdx.x * 256;

    int wm = wid & 3;              // 4 warps along M (32 rows each)
    int wn = wid >> 2;             // 4 warps along N (64 cols each)

    float acc[2][8][4];
#pragma unroll
    for (int i = 0; i < 2; i++)
#pragma unroll
        for (int j = 0; j < 8; j++)
#pragma unroll
            for (int t = 0; t < 4; t++) acc[i][j][t] = 0.f;

    mg_load(sb,           Ah, Al, Bh, Bl, m0, n0, 0,     tid); CP_COMMIT();
    mg_load(sb + STAGE_B, Ah, Al, Bh, Bl, m0, n0, MG_BK, tid); CP_COMMIT();

    int a_row  = wm * 32 + (lane & 15);
    uint32_t a_koff = ((lane >> 4) & 1) * 16;
    int b_row  = wn * 64 + (lane & 7) + (((lane >> 4) & 1) << 3);
    uint32_t b_koff = ((lane >> 3) & 1) * 16;

    for (int c = 0; c < MG_NC; c++) {
        if (c + 2 >= MG_NC) { CP_WAIT0(); } else { CP_WAIT1(); }
        __syncthreads();
        uint32_t u = sb + (uint32_t)(c % 3) * STAGE_B;
        uint32_t uAh = u, uAl = u + MGA_BYTES;
        uint32_t uBh = u + 2 * MGA_BYTES, uBl = uBh + MGB_BYTES;

#pragma unroll
        for (int ks = 0; ks < 2; ks++) {
            uint32_t kb = ks * 32;
            uint32_t ahf[8], alf[8];           // m32k16 hi + lo
            uint32_t ao = (uint32_t)a_row * 80 + a_koff + kb;
            ldsm4(ahf,     uAh + ao);
            ldsm4(ahf + 4, uAh + ao + 16 * 80);
            ldsm4(alf,     uAl + ao);
            ldsm4(alf + 4, uAl + ao + 16 * 80);
#pragma unroll
            for (int j = 0; j < 4; j++) {
                uint32_t bhf[4], blf[4];
                uint32_t bo = (uint32_t)(b_row + j * 16) * 80 + b_koff + kb;
                ldsm4(bhf, uBh + bo);
                ldsm4(blf, uBl + bo);
#pragma unroll
                for (int i = 0; i < 2; i++) {
                    mma_bf16(acc[i][2 * j],     ahf + 4 * i, &bhf[0]);
                    mma_bf16(acc[i][2 * j + 1], ahf + 4 * i, &bhf[2]);
                    mma_bf16(acc[i][2 * j],     ahf + 4 * i, &blf[0]);
                    mma_bf16(acc[i][2 * j + 1], ahf + 4 * i, &blf[2]);
                    mma_bf16(acc[i][2 * j],     alf + 4 * i, &bhf[0]);
                    mma_bf16(acc[i][2 * j + 1], alf + 4 * i, &bhf[2]);
                }
            }
        }

        if (c + 2 < MG_NC) {
            mg_load(sb + (uint32_t)((c + 2) % 3) * STAGE_B,
                    Ah, Al, Bh, Bl, m0, n0, (c + 2) * MG_BK, tid);
            CP_COMMIT();
        }
    }

    int r0 = m0 + wm * 32 + (lane >> 2);
    int c0 = n0 + wn * 64 + (lane & 3) * 2;

    if (!qkv_mode) {
#pragma unroll
        for (int i = 0; i < 2; i++) {
#pragma unroll
            for (int j = 0; j < 8; j++) {
                int gn = c0 + j * 8;
#pragma unroll
                for (int half = 0; half < 2; half++) {
                    int gm = r0 + i * 16 + half * 8;
                    *(float2*)&Cf[(size_t)gm * D_DIM + gn] =
                        make_float2(acc[i][j][2 * half], acc[i][j][2 * half + 1]);
                }
            }
        }
    } else {
        __nv_bfloat16* HZ = (z == 0) ? H0 : ((z == 1) ? H1 : H2);
        __nv_bfloat16* LZ = (z == 0) ? L0 : ((z == 1) ? L1 : L2);
        const float qscale = 0.08838834764831845f;  // 1/sqrt(128)
#pragma unroll
        for (int j = 0; j < 8; j++) {
            int gn = c0 + j * 8;
            int hd = gn & 127;
            int h  = gn >> 7;
            int pidx = hd >> 1;
#pragma unroll
            for (int i = 0; i < 2; i++) {
#pragma unroll
                for (int half = 0; half < 2; half++) {
                    int gm = r0 + i * 16 + half * 8;
                    int b = gm >> 11, s = gm & 2047;
                    float x0 = acc[i][j][2 * half];
                    float x1 = acc[i][j][2 * half + 1];
                    float y0 = x0, y1 = x1;
                    if (z < 2) {
                        float4 t = Rope[s * 64 + pidx];
                        y0 = x0 * t.x - x1 * t.y;   // even: x*cos - x_odd*sin
                        y1 = x1 * t.z + x0 * t.w;   // odd:  x*cos + x_even*sin
                        if (z == 0) { y0 *= qscale; y1 *= qscale; }
                    }
                    __nv_bfloat16 hh0 = __float2bfloat16(y0);
                    __nv_bfloat16 hh1 = __float2bfloat16(y1);
                    __nv_bfloat16 ll0 = __float2bfloat16(y0 - __bfloat162float(hh0));
                    __nv_bfloat16 ll1 = __float2bfloat16(y1 - __bfloat162float(hh1));
                    size_t off = (((size_t)(b * H_NUM + h)) * S_LEN + s) * HD + hd;
                    *(__nv_bfloat162*)(HZ + off) = __nv_bfloat162(hh0, hh1);
                    *(__nv_bfloat162*)(LZ + off) = __nv_bfloat162(ll0, ll1);
                }
            }
        }
    }
}

// ---------------------------------------------------------------------------
// fp32 -> (hi, lo) bf16 split, 4 elems/thread (x input only)
// ---------------------------------------------------------------------------
__global__ void split_kernel(const float* __restrict__ X,
                             __nv_bfloat16* __restrict__ Hh,
                             __nv_bfloat16* __restrict__ Ll)
{
    size_t i = ((size_t)blockIdx.x * blockDim.x + threadIdx.x) * 4;
    float4 v = *(const float4*)(X + i);
    __nv_bfloat16 h0 = __float2bfloat16(v.x);
    __nv_bfloat16 h1 = __float2bfloat16(v.y);
    __nv_bfloat16 h2 = __float2bfloat16(v.z);
    __nv_bfloat16 h3 = __float2bfloat16(v.w);
    __nv_bfloat16 l0 = __float2bfloat16(v.x - __bfloat162float(h0));
    __nv_bfloat16 l1 = __float2bfloat16(v.y - __bfloat162float(h1));
    __nv_bfloat16 l2 = __float2bfloat16(v.z - __bfloat162float(h2));
    __nv_bfloat16 l3 = __float2bfloat16(v.w - __bfloat162float(h3));
    __nv_bfloat162* hp = (__nv_bfloat162*)(Hh + i);
    __nv_bfloat162* lp = (__nv_bfloat162*)(Ll + i);
    hp[0] = __nv_bfloat162(h0, h1); hp[1] = __nv_bfloat162(h2, h3);
    lp[0] = __nv_bfloat162(l0, l1); lp[1] = __nv_bfloat162(l2, l3);
}

// ---------------------------------------------------------------------------
// Weight transpose + split (unchanged)
// ---------------------------------------------------------------------------
__global__ void wtrans_kernel(const float* __restrict__ W0, const float* __restrict__ W1,
                              const float* __restrict__ W2, const float* __restrict__ W3,
                              __nv_bfloat16* __restrict__ TH,
                              __nv_bfloat16* __restrict__ TL)
{
    __shared__ float t[32][33];
    int z = blockIdx.z;
    const float* W = (z == 0) ? W0 : (z == 1 ? W1 : (z == 2 ? W2 : W3));
    __nv_bfloat16* th = TH + (size_t)z * D_DIM * KDIM;
    __nv_bfloat16* tl = TL + (size_t)z * D_DIM * KDIM;
    int k0 = blockIdx.y * 32, n0 = blockIdx.x * 32;
    int tx = threadIdx.x, ty = threadIdx.y;
#pragma unroll
    for (int i = 0; i < 4; i++)
        t[ty + 8 * i][tx] = W[(size_t)(k0 + ty + 8 * i) * D_DIM + n0 + tx];
    __syncthreads();
#pragma unroll
    for (int i = 0; i < 4; i++) {
        float v = t[tx][ty + 8 * i];
        __nv_bfloat16 h = __float2bfloat16(v);
        __nv_bfloat16 l = __float2bfloat16(v - __bfloat162float(h));
        size_t o = (size_t)(n0 + ty + 8 * i) * KDIM + k0 + tx;
        th[o] = h;
        tl[o] = l;
    }
}

// ---------------------------------------------------------------------------
// Tensor-core flash attention (bf16 split, fp32 softmax), causal.
// UNCHANGED (passed; 352us, tensor=50.9%).
// ---------------------------------------------------------------------------
#define FR_STRIDE 272
#define FQ_BYTES  (128 * FR_STRIDE)
#define FKV_MAT   (64 * FR_STRIDE)
#define FSTAGE    (4 * FKV_MAT)
#define FA2_SMEM  (2 * FQ_BYTES + 2 * FSTAGE)

__device__ __forceinline__ void fa_load_kv(
    uint32_t st, const __nv_bfloat16* KH, const __nv_bfloat16* KL,
    const __nv_bfloat16* VH, const __nv_bfloat16* VL,
    int bh, int kb, int tid)
{
#pragma unroll
    for (int i = 0; i < 4; i++) {
        int idx = tid + i * 256;
        int r = idx >> 4, ch = idx & 15;
        uint32_t off = (uint32_t)r * FR_STRIDE + ch * 16;
        size_t g = ((size_t)bh * S_LEN + kb * 64 + r) * HD + ch * 8;
        cp16(st + off,               KH + g);
        cp16(st + FKV_MAT + off,     KL + g);
        cp16(st + 2 * FKV_MAT + off, VH + g);
        cp16(st + 3 * FKV_MAT + off, VL + g);
    }
}

__global__ __launch_bounds__(256, 1)
void flash_mma_kernel(const __nv_bfloat16* __restrict__ QH,
                      const __nv_bfloat16* __restrict__ QL,
                      const __nv_bfloat16* __restrict__ KH,
                      const __nv_bfloat16* __restrict__ KL,
                      const __nv_bfloat16* __restrict__ VH,
                      const __nv_bfloat16* __restrict__ VL,
                      __nv_bfloat16* __restrict__ AH,
                      __nv_bfloat16* __restrict__ AL)
{
    extern __shared__ __align__(256) char smem[];
    uint32_t sb = smem_u32(smem);
    const uint32_t uQH = sb, uQL = sb + FQ_BYTES;
    const uint32_t uST0 = sb + 2 * FQ_BYTES;

    int tid = threadIdx.x;
    int wid = tid >> 5, lane = tid & 31;
    int qb = 15 - blockIdx.x;
    int bh = blockIdx.y;
    int nkb = 2 * qb + 2;

#pragma unroll
    for (int i = 0; i < 8; i++) {
        int idx = tid + i * 256;
        int r = idx >> 4, ch = idx & 15;
        uint32_t off = (uint32_t)r * FR_STRIDE + ch * 16;
        size_t g = ((size_t)bh * S_LEN + qb * 128 + r) * HD + ch * 8;
        cp16(uQH + off, QH + g);
        cp16(uQL + off, QL + g);
    }
    CP_COMMIT();
    fa_load_kv(uST0, KH, KL, VH, VL, bh, 0, tid); CP_COMMIT();
    if (nkb > 1) { fa_load_kv(uST0 + FSTAGE, KH, KL, VH, VL, bh, 1, tid); CP_COMMIT(); }

    float accO[16][4];
#pragma unroll
    for (int j = 0; j < 16; j++)
#pragma unroll
        for (int t = 0; t < 4; t++) accO[j][t] = 0.f;
    float m0v = -INFINITY, m1v = -INFINITY, l0v = 0.f, l1v = 0.f;

    uint32_t q_ao = (uint32_t)(wid * 16 + (lane & 15)) * FR_STRIDE + ((lane >> 4) & 1) * 16;
    uint32_t k_bo = (uint32_t)((lane & 7) + (((lane >> 4) & 1) << 3)) * FR_STRIDE
                    + ((lane >> 3) & 1) * 16;
    uint32_t v_to = (uint32_t)(lane & 15) * FR_STRIDE + ((lane >> 4) & 1) * 16;

    if (nkb > 1) { CP_WAIT1(); } else { CP_WAIT0(); }
    __syncthreads();

    for (int kb = 0; kb < nkb; kb++) {
        uint32_t st = uST0 + (uint32_t)(kb & 1) * FSTAGE;
        uint32_t stKH = st, stKL = st + FKV_MAT;
        uint32_t stVH = st + 2 * FKV_MAT, stVL = st + 3 * FKV_MAT;

        float accS[8][4];
#pragma unroll
        for (int j = 0; j < 8; j++)
#pragma unroll
            for (int t = 0; t < 4; t++) accS[j][t] = 0.f;

#pragma unroll
        for (int ks = 0; ks < 8; ks++) {
            uint32_t qh[4], ql[4];
            ldsm4(qh, uQH + q_ao + ks * 32);
            ldsm4(ql, uQL + q_ao + ks * 32);
#pragma unroll
            for (int j = 0; j < 4; j++) {
                uint32_t kh[4], kl[4];
                uint32_t bo = k_bo + (uint32_t)j * 16 * FR_STRIDE + ks * 32;
                ldsm4(kh, stKH + bo);
                ldsm4(kl, stKL + bo);
                mma_bf16(accS[2 * j],     qh, &kh[0]);
                mma_bf16(accS[2 * j + 1], qh, &kh[2]);
                mma_bf16(accS[2 * j],     qh, &kl[0]);
                mma_bf16(accS[2 * j + 1], qh, &kl[2]);
                mma_bf16(accS[2 * j],     ql, &kh[0]);
                mma_bf16(accS[2 * j + 1], ql, &kh[2]);
            }
        }

        if (kb >= 2 * qb) {
            int grow = qb * 128 + wid * 16 + (lane >> 2);
#pragma unroll
            for (int j = 0; j < 8; j++) {
                int col = kb * 64 + j * 8 + ((lane & 3) << 1);
                if (col     > grow)     accS[j][0] = -INFINITY;
                if (col + 1 > grow)     accS[j][1] = -INFINITY;
                if (col     > grow + 8) accS[j][2] = -INFINITY;
                if (col + 1 > grow + 8) accS[j][3] = -INFINITY;
            }
        }

        float rm0 = -INFINITY, rm1 = -INFINITY;
#pragma unroll
        for (int j = 0; j < 8; j++) {
            rm0 = fmaxf(rm0, fmaxf(accS[j][0], accS[j][1]));
            rm1 = fmaxf(rm1, fmaxf(accS[j][2], accS[j][3]));
        }
        rm0 = fmaxf(rm0, __shfl_xor_sync(0xffffffffu, rm0, 1));
        rm0 = fmaxf(rm0, __shfl_xor_sync(0xffffffffu, rm0, 2));
        rm1 = fmaxf(rm1, __shfl_xor_sync(0xffffffffu, rm1, 1));
        rm1 = fmaxf(rm1, __shfl_xor_sync(0xffffffffu, rm1, 2));

        float mn0 = fmaxf(m0v, rm0), mn1 = fmaxf(m1v, rm1);
        float al0 = __expf(m0v - mn0), al1 = __expf(m1v - mn1);
        m0v = mn0; m1v = mn1;

        float rs0 = 0.f, rs1 = 0.f;
#pragma unroll
        for (int j = 0; j < 8; j++) {
            accS[j][0] = __expf(accS[j][0] - mn0);
            accS[j][1] = __expf(accS[j][1] - mn0);
            accS[j][2] = __expf(accS[j][2] - mn1);
            accS[j][3] = __expf(accS[j][3] - mn1);
            rs0 += accS[j][0] + accS[j][1];
            rs1 += accS[j][2] + accS[j][3];
        }
        rs0 += __shfl_xor_sync(0xffffffffu, rs0, 1);
        rs0 += __shfl_xor_sync(0xffffffffu, rs0, 2);
        rs1 += __shfl_xor_sync(0xffffffffu, rs1, 1);
        rs1 += __shfl_xor_sync(0xffffffffu, rs1, 2);
        l0v = l0v * al0 + rs0;
        l1v = l1v * al1 + rs1;

#pragma unroll
        for (int j = 0; j < 16; j++) {
            accO[j][0] *= al0; accO[j][1] *= al0;
            accO[j][2] *= al1; accO[j][3] *= al1;
        }

        uint32_t pa_h[8][2], pa_l[8][2];
#pragma unroll
        for (int j = 0; j < 8; j++) {
            __nv_bfloat16 h0 = __float2bfloat16(accS[j][0]);
            __nv_bfloat16 h1 = __float2bfloat16(accS[j][1]);
            __nv_bfloat16 h2 = __float2bfloat16(accS[j][2]);
            __nv_bfloat16 h3 = __float2bfloat16(accS[j][3]);
            __nv_bfloat16 e0 = __float2bfloat16(accS[j][0] - __bfloat162float(h0));
            __nv_bfloat16 e1 = __float2bfloat16(accS[j][1] - __bfloat162float(h1));
            __nv_bfloat16 e2 = __float2bfloat16(accS[j][2] - __bfloat162float(h2));
            __nv_bfloat16 e3 = __float2bfloat16(accS[j][3] - __bfloat162float(h3));
            pa_h[j][0] = ((uint32_t)__bfloat16_as_ushort(h1) << 16) | __bfloat16_as_ushort(h0);
            pa_h[j][1] = ((uint32_t)__bfloat16_as_ushort(h3) << 16) | __bfloat16_as_ushort(h2);
            pa_l[j][0] = ((uint32_t)__bfloat16_as_ushort(e1) << 16) | __bfloat16_as_ushort(e0);
            pa_l[j][1] = ((uint32_t)__bfloat16_as_ushort(e3) << 16) | __bfloat16_as_ushort(e2);
        }

#pragma unroll
        for (int ks = 0; ks < 4; ks++) {
            uint32_t ah4[4] = { pa_h[2 * ks][0], pa_h[2 * ks][1],
                                pa_h[2 * ks + 1][0], pa_h[2 * ks + 1][1] };
            uint32_t al4[4] = { pa_l[2 * ks][0], pa_l[2 * ks][1],
                                pa_l[2 * ks + 1][0], pa_l[2 * ks + 1][1] };
#pragma unroll
            for (int j2 = 0; j2 < 8; j2++) {
                uint32_t vh[4], vl[4];
                uint32_t vo = v_to + (uint32_t)ks * 16 * FR_STRIDE + j2 * 32;
                ldsm4t(vh, stVH + vo);
                ldsm4t(vl, stVL + vo);
                mma_bf16(accO[2 * j2],     ah4, &vh[0]);
                mma_bf16(accO[2 * j2 + 1], ah4, &vh[2]);
                mma_bf16(accO[2 * j2],     ah4, &vl[0]);
                mma_bf16(accO[2 * j2 + 1], ah4, &vl[2]);
                mma_bf16(accO[2 * j2],     al4, &vh[0]);
                mma_bf16(accO[2 * j2 + 1], al4, &vh[2]);
            }
        }

        __syncthreads();
        if (kb + 2 < nkb) {
            fa_load_kv(st, KH, KL, VH, VL, bh, kb + 2, tid);
            CP_COMMIT();
        }
        if (kb + 1 < nkb) {
            if (kb + 2 < nkb) { CP_WAIT1(); } else { CP_WAIT0(); }
            __syncthreads();
        }
    }

    int b = bh >> 4, h = bh & 15;
    int srow = qb * 128 + wid * 16 + (lane >> 2);
    float inv0 = 1.0f / l0v, inv1 = 1.0f / l1v;
#pragma unroll
    for (int j = 0; j < 16; j++) {
        int col = h * HD + j * 8 + ((lane & 3) << 1);
        size_t o0 = ((size_t)b * S_LEN + srow) * D_DIM + col;
        size_t o1 = ((size_t)b * S_LEN + srow + 8) * D_DIM + col;
        float v00 = accO[j][0] * inv0, v01 = accO[j][1] * inv0;
        float v10 = accO[j][2] * inv1, v11 = accO[j][3] * inv1;
        __nv_bfloat16 h00 = __float2bfloat16(v00);
        __nv_bfloat16 h01 = __float2bfloat16(v01);
        __nv_bfloat16 h10 = __float2bfloat16(v10);
        __nv_bfloat16 h11 = __float2bfloat16(v11);
        __nv_bfloat16 l00 = __float2bfloat16(v00 - __bfloat162float(h00));
        __nv_bfloat16 l01 = __float2bfloat16(v01 - __bfloat162float(h01));
        __nv_bfloat16 l10 = __float2bfloat16(v10 - __bfloat162float(h10));
        __nv_bfloat16 l11 = __float2bfloat16(v11 - __bfloat162float(h11));
        *(__nv_bfloat162*)(AH + o0) = __nv_bfloat162(h00, h01);
        *(__nv_bfloat162*)(AL + o0) = __nv_bfloat162(l00, l01);
        *(__nv_bfloat162*)(AH + o1) = __nv_bfloat162(h10, h11);
        *(__nv_bfloat162*)(AL + o1) = __nv_bfloat162(l10, l11);
    }
}

// ---------------------------------------------------------------------------
extern "C" void kernel_launch(void* const* d_in, const int* in_sizes, int n_in,
                              void* d_out, int out_size)
{
    const float* x  = (const float*)d_in[0];
    const float* Wq = (const float*)d_in[1];
    const float* Wk = (const float*)d_in[2];
    const float* Wv = (const float*)d_in[3];
    const float* Wo = (const float*)d_in[4];
    float* out = (float*)d_out;

    __nv_bfloat16 *pah, *pal, *pwh, *pwl;
    __nv_bfloat16 *pqh, *pql, *pkh, *pkl, *pvh, *pvl;
    float4* prt;
    cudaGetSymbolAddress((void**)&pah, g_ah);
    cudaGetSymbolAddress((void**)&pal, g_al);
    cudaGetSymbolAddress((void**)&pwh, g_wth);
    cudaGetSymbolAddress((void**)&pwl, g_wtl);
    cudaGetSymbolAddress((void**)&pqh, g_qh);
    cudaGetSymbolAddress((void**)&pql, g_ql);
    cudaGetSymbolAddress((void**)&pkh, g_kh);
    cudaGetSymbolAddress((void**)&pkl, g_kl);
    cudaGetSymbolAddress((void**)&pvh, g_vh);
    cudaGetSymbolAddress((void**)&pvl, g_vl);
    cudaGetSymbolAddress((void**)&prt, g_rope);

    cudaFuncSetAttribute(mma_gemm_kernel,
                         cudaFuncAttributeMaxDynamicSharedMemorySize, MG_SMEM);
    cudaFuncSetAttribute(flash_mma_kernel,
                         cudaFuncAttributeMaxDynamicSharedMemorySize, FA2_SMEM);

    // 0) bf16 split of x
    split_kernel<<<(M_ROWS * KDIM / 4) / 256, 256>>>(x, pah, pal);

    // 1) weight transpose + split
    wtrans_kernel<<<dim3(D_DIM / 32, KDIM / 32, 4), dim3(32, 8)>>>(
        Wq, Wk, Wv, Wo, pwh, pwl);

    // 2) RoPE cos/sin table
    ropetab_kernel<<<(S_LEN * 64) / 256, 256>>>(prt);

    // 3) QKV projections + fused RoPE(table)/scale/bf16-split epilogue
    mma_gemm_kernel<<<dim3(D_DIM / 256, M_ROWS / 128, 3), MG_THREADS, MG_SMEM>>>(
        pah, pal, pwh, pwl, prt,
        pqh, pql, pkh, pkl, pvh, pvl, (float*)nullptr, 0, 1);

    // 4) tensor-core causal flash attention (writes bf16 hi/lo attn-out)
    flash_mma_kernel<<<dim3(S_LEN / 128, BH_NUM), 256, FA2_SMEM>>>(
        pqh, pql, pkh, pkl, pvh, pvl, pah, pal);

    // 5) O projection -> d_out (fp32)
    mma_gemm_kernel<<<dim3(D_DIM / 256, M_ROWS / 128, 1), MG_THREADS, MG_SMEM>>>(
        pah, pal, pwh, pwl, prt,
        (__nv_bfloat16*)nullptr, (__nv_bfloat16*)nullptr,
        (__nv_bfloat16*)nullptr, (__nv_bfloat16*)nullptr,
        (__nv_bfloat16*)nullptr, (__nv_bfloat16*)nullptr,
        out, 3, 0);
}